// round 1
// baseline (speedup 1.0000x reference)
#include <cuda_runtime.h>

// Problem constants
#define INSZ   128
#define OUTSZ  128
#define HID    8
#define BATCH  1024
#define NSUB   (INSZ * OUTSZ)

#define NCHUNK 8
#define BC     (BATCH / NCHUNK)   // 128 batch elems per block
#define NF     97                 // floats of weights per subnet

// Transposed weights: [o][field][i]  (field-major so lane=i loads coalesce)
__device__ float g_wt[(size_t)OUTSZ * NF * INSZ];

typedef unsigned long long u64;

__device__ __forceinline__ u64 pk(float a, float b) {
    u64 r; asm("mov.b64 %0, {%1, %2};" : "=l"(r) : "f"(a), "f"(b)); return r;
}
__device__ __forceinline__ void upk(u64 v, float& a, float& b) {
    asm("mov.b64 {%0, %1}, %2;" : "=f"(a), "=f"(b) : "l"(v));
}
__device__ __forceinline__ u64 ffma2(u64 a, u64 b, u64 c) {
    u64 d; asm("fma.rn.f32x2 %0, %1, %2, %3;" : "=l"(d) : "l"(a), "l"(b), "l"(c)); return d;
}

// ---------------------------------------------------------------------------
// Prep: scatter-gather original weights into field-major transposed layout.
// grid(128 o), block(128 i). Reads strided, writes coalesced. Runs every call
// (deterministic, ~few microseconds, L2-resident).
// ---------------------------------------------------------------------------
__global__ void prep_kernel(const float* __restrict__ W1, const float* __restrict__ b1,
                            const float* __restrict__ W2, const float* __restrict__ b2,
                            const float* __restrict__ W3, const float* __restrict__ b3) {
    const int o = blockIdx.x;
    const int i = threadIdx.x;
    const int n = i * OUTSZ + o;           // subnet id
    float* dst = g_wt + (size_t)o * (NF * INSZ) + i;

#pragma unroll
    for (int h = 0; h < 8; h++) dst[h * INSZ] = W1[n * 8 + h];          // f 0..7
#pragma unroll
    for (int h = 0; h < 8; h++) dst[(8 + h) * INSZ] = b1[n * 8 + h];    // f 8..15
#pragma unroll
    for (int j = 0; j < 8; j++)
#pragma unroll
        for (int k = 0; k < 8; k++)
            dst[(16 + j * 8 + k) * INSZ] = W2[n * 64 + j * 8 + k];      // f 16..79
#pragma unroll
    for (int j = 0; j < 8; j++) dst[(80 + j) * INSZ] = b2[n * 8 + j];   // f 80..87
#pragma unroll
    for (int k = 0; k < 8; k++) dst[(88 + k) * INSZ] = W3[n * 8 + k];   // f 88..95
    dst[96 * INSZ] = b3[n];                                             // f 96
}

// ---------------------------------------------------------------------------
// Main: block = (o, batch-chunk of 128); thread = input feature i.
// All weights live in f32x2-packed registers (packed over hidden dim, so the
// packed weights are loop-invariant). Per batch element: 40 FFMA2 + relu.
// Contributions block-reduced over i via padded smem (no atomics).
// ---------------------------------------------------------------------------
__global__ void __launch_bounds__(128, 3)
mlpkan_main(const float* __restrict__ x, float* __restrict__ out) {
    const int o     = blockIdx.x;
    const int chunk = blockIdx.y;
    const int i     = threadIdx.x;

    __shared__ float red[32 * 129];   // [b_sub][i] padded: conflict-free R/W

    // ---- load this thread's 97 weights (fully coalesced: lane = i) ----
    const float* wt = g_wt + (size_t)o * (NF * INSZ) + i;
    float w1[8], B1[8], w2[8][8], B2[8], w3[8], b3v;
#pragma unroll
    for (int h = 0; h < 8; h++) w1[h] = wt[h * INSZ];
#pragma unroll
    for (int h = 0; h < 8; h++) B1[h] = wt[(8 + h) * INSZ];
#pragma unroll
    for (int j = 0; j < 8; j++)
#pragma unroll
        for (int k = 0; k < 8; k++) w2[j][k] = wt[(16 + j * 8 + k) * INSZ];
#pragma unroll
    for (int j = 0; j < 8; j++) B2[j] = wt[(80 + j) * INSZ];
#pragma unroll
    for (int k = 0; k < 8; k++) w3[k] = wt[(88 + k) * INSZ];
    b3v = wt[96 * INSZ];

    // ---- pre-pack all loop-invariant f32x2 operands (hidden dim pairs) ----
    u64 w1p[4], b1p[4], w2p[4][8], b2p[4], w3p[4], b3p;
#pragma unroll
    for (int p = 0; p < 4; p++) {
        w1p[p] = pk(w1[2 * p], w1[2 * p + 1]);
        b1p[p] = pk(B1[2 * p], B1[2 * p + 1]);
        b2p[p] = pk(B2[2 * p], B2[2 * p + 1]);
        w3p[p] = pk(w3[2 * p], w3[2 * p + 1]);
#pragma unroll
        for (int k = 0; k < 8; k++)
            w2p[p][k] = pk(w2[2 * p][k], w2[2 * p + 1][k]);
    }
    b3p = pk(b3v, 0.0f);   // bias lands in the low half of the final dot

    const float* xp = x + (size_t)chunk * BC * INSZ + i;

#pragma unroll 1
    for (int sub = 0; sub < 4; sub++) {
#pragma unroll 2
        for (int bb = 0; bb < 32; bb++) {
            float v = xp[(sub * 32 + bb) * INSZ];      // coalesced, L1/L2 hot
            u64 vp = pk(v, v);

            // layer 1: h1 = relu(w1*v + b1), produce splatted pairs s[k]
            u64 s[8];
#pragma unroll
            for (int p = 0; p < 4; p++) {
                u64 t = ffma2(w1p[p], vp, b1p[p]);
                float ta, tb; upk(t, ta, tb);
                ta = fmaxf(ta, 0.0f);
                tb = fmaxf(tb, 0.0f);
                s[2 * p]     = pk(ta, ta);
                s[2 * p + 1] = pk(tb, tb);
            }

            // layer 2: 4 packed output-pairs, 8-deep K accumulation each
            u64 h[4];
#pragma unroll
            for (int q = 0; q < 4; q++) {
                u64 acc = ffma2(w2p[q][0], s[0], b2p[q]);
#pragma unroll
                for (int k = 1; k < 8; k++) acc = ffma2(w2p[q][k], s[k], acc);
                float ha, hb; upk(acc, ha, hb);
                h[q] = pk(fmaxf(ha, 0.0f), fmaxf(hb, 0.0f));
            }

            // layer 3: packed dot over hidden, horizontal add folds b3
            u64 a = ffma2(w3p[0], h[0], b3p);
            a = ffma2(w3p[1], h[1], a);
            a = ffma2(w3p[2], h[2], a);
            a = ffma2(w3p[3], h[3], a);
            float aa, ab; upk(a, aa, ab);

            red[bb * 129 + i] = aa + ab;
        }
        __syncthreads();

        // reduce over i (128 contributions) for each of 32 batch elems
        if (i < 32) {
            const float* rr = &red[i * 129];
            float s0 = 0.f, s1 = 0.f, s2 = 0.f, s3 = 0.f;
#pragma unroll
            for (int c = 0; c < 128; c += 4) {
                s0 += rr[c + 0]; s1 += rr[c + 1];
                s2 += rr[c + 2]; s3 += rr[c + 3];
            }
            out[(size_t)(chunk * BC + sub * 32 + i) * OUTSZ + o] = (s0 + s1) + (s2 + s3);
        }
        __syncthreads();
    }
}

// ---------------------------------------------------------------------------
extern "C" void kernel_launch(void* const* d_in, const int* in_sizes, int n_in,
                              void* d_out, int out_size) {
    const float* x  = (const float*)d_in[0];
    const float* W1 = (const float*)d_in[1];
    const float* b1 = (const float*)d_in[2];
    const float* W2 = (const float*)d_in[3];
    const float* b2 = (const float*)d_in[4];
    const float* W3 = (const float*)d_in[5];
    const float* b3 = (const float*)d_in[6];
    float* out = (float*)d_out;

    prep_kernel<<<OUTSZ, INSZ>>>(W1, b1, W2, b2, W3, b3);
    mlpkan_main<<<dim3(OUTSZ, NCHUNK), INSZ>>>(x, out);
}

// round 2
// speedup vs baseline: 1.1804x; 1.1804x over previous
#include <cuda_runtime.h>

// Problem constants
#define INSZ   128
#define OUTSZ  128
#define HID    8
#define BATCH  1024
#define NSUB   (INSZ * OUTSZ)

#define NCHUNK 8
#define BC     (BATCH / NCHUNK)   // 128 batch elems per block
#define NF     97                 // floats of weights per subnet

// Transposed weights: [o][field][i]  (field-major so lane=i loads coalesce)
__device__ float g_wt[(size_t)OUTSZ * NF * INSZ];

typedef unsigned long long u64;

__device__ __forceinline__ u64 pk(float a, float b) {
    u64 r; asm("mov.b64 %0, {%1, %2};" : "=l"(r) : "f"(a), "f"(b)); return r;
}
__device__ __forceinline__ void upk(u64 v, float& a, float& b) {
    asm("mov.b64 {%0, %1}, %2;" : "=f"(a), "=f"(b) : "l"(v));
}
__device__ __forceinline__ u64 ffma2(u64 a, u64 b, u64 c) {
    u64 d; asm("fma.rn.f32x2 %0, %1, %2, %3;" : "=l"(d) : "l"(a), "l"(b), "l"(c)); return d;
}
__device__ __forceinline__ u64 fmul2(u64 a, u64 b) {
    u64 d; asm("mul.rn.f32x2 %0, %1, %2;" : "=l"(d) : "l"(a), "l"(b)); return d;
}

// ---------------------------------------------------------------------------
// Prep: scatter-gather original weights into field-major transposed layout.
// ---------------------------------------------------------------------------
__global__ void prep_kernel(const float* __restrict__ W1, const float* __restrict__ b1,
                            const float* __restrict__ W2, const float* __restrict__ b2,
                            const float* __restrict__ W3, const float* __restrict__ b3) {
    const int o = blockIdx.x;
    const int i = threadIdx.x;
    const int n = i * OUTSZ + o;           // subnet id
    float* dst = g_wt + (size_t)o * (NF * INSZ) + i;

#pragma unroll
    for (int h = 0; h < 8; h++) dst[h * INSZ] = W1[n * 8 + h];          // f 0..7
#pragma unroll
    for (int h = 0; h < 8; h++) dst[(8 + h) * INSZ] = b1[n * 8 + h];    // f 8..15
#pragma unroll
    for (int j = 0; j < 8; j++)
#pragma unroll
        for (int k = 0; k < 8; k++)
            dst[(16 + j * 8 + k) * INSZ] = W2[n * 64 + j * 8 + k];      // f 16..79
#pragma unroll
    for (int j = 0; j < 8; j++) dst[(80 + j) * INSZ] = b2[n * 8 + j];   // f 80..87
#pragma unroll
    for (int k = 0; k < 8; k++) dst[(88 + k) * INSZ] = W3[n * 8 + k];   // f 88..95
    dst[96 * INSZ] = b3[n];                                             // f 96
}

// ---------------------------------------------------------------------------
// Main: block = (o, batch-chunk of 128); thread = input feature i.
// f32x2-packed weights over hidden dim (loop-invariant registers).
// x loads software-pipelined 8 deep; reduction spread over all 128 threads.
// ---------------------------------------------------------------------------
__global__ void __launch_bounds__(128, 3)
mlpkan_main(const float* __restrict__ x, float* __restrict__ out) {
    const int o     = blockIdx.x;
    const int chunk = blockIdx.y;
    const int i     = threadIdx.x;

    __shared__ float red[32 * 129];   // [b_sub][i] padded: conflict-free R/W
    __shared__ float pr[4 * 33];      // partial sums [quarter][bb]

    // ---- load this thread's 97 weights (fully coalesced: lane = i) ----
    const float* wt = g_wt + (size_t)o * (NF * INSZ) + i;
    float w1[8], B1[8], w2[8][8], B2[8], w3[8], b3v;
#pragma unroll
    for (int h = 0; h < 8; h++) w1[h] = wt[h * INSZ];
#pragma unroll
    for (int h = 0; h < 8; h++) B1[h] = wt[(8 + h) * INSZ];
#pragma unroll
    for (int j = 0; j < 8; j++)
#pragma unroll
        for (int k = 0; k < 8; k++) w2[j][k] = wt[(16 + j * 8 + k) * INSZ];
#pragma unroll
    for (int j = 0; j < 8; j++) B2[j] = wt[(80 + j) * INSZ];
#pragma unroll
    for (int k = 0; k < 8; k++) w3[k] = wt[(88 + k) * INSZ];
    b3v = wt[96 * INSZ];

    // ---- pre-pack all loop-invariant f32x2 operands (hidden dim pairs) ----
    u64 w1p[4], b1p[4], w2p[4][8], b2p[4], w3p[4], b3p;
#pragma unroll
    for (int p = 0; p < 4; p++) {
        w1p[p] = pk(w1[2 * p], w1[2 * p + 1]);
        b1p[p] = pk(B1[2 * p], B1[2 * p + 1]);
        b2p[p] = pk(B2[2 * p], B2[2 * p + 1]);
        w3p[p] = pk(w3[2 * p], w3[2 * p + 1]);
#pragma unroll
        for (int k = 0; k < 8; k++)
            w2p[p][k] = pk(w2[2 * p][k], w2[2 * p + 1][k]);
    }
    b3p = pk(b3v, 0.0f);   // bias lands in the low half of chain 0

    const float* xp = x + (size_t)chunk * BC * INSZ + i;

    // ---- 8-deep rolling register prefetch of x ----
    float vbuf[8];
#pragma unroll
    for (int p = 0; p < 8; p++) vbuf[p] = xp[(size_t)p * INSZ];

#pragma unroll 1
    for (int sub = 0; sub < 4; sub++) {
#pragma unroll 1
        for (int g = 0; g < 4; g++) {
#pragma unroll
            for (int u = 0; u < 8; u++) {
                const int b = sub * 32 + g * 8 + u;   // batch elem within chunk
                float v = vbuf[u];
                const int pb = b + 8;                  // prefetch 8 ahead
                if (pb < BC) vbuf[u] = xp[(size_t)pb * INSZ];

                u64 vp = pk(v, v);

                // layer 1: h1 = relu(w1*v + b1), produce splatted pairs s[k]
                u64 s[8];
#pragma unroll
                for (int p = 0; p < 4; p++) {
                    u64 t = ffma2(w1p[p], vp, b1p[p]);
                    float ta, tb; upk(t, ta, tb);
                    ta = fmaxf(ta, 0.0f);
                    tb = fmaxf(tb, 0.0f);
                    s[2 * p]     = pk(ta, ta);
                    s[2 * p + 1] = pk(tb, tb);
                }

                // layer 2: 4 packed output-pairs, 8-deep K accumulation each
                u64 h[4];
#pragma unroll
                for (int q = 0; q < 4; q++) {
                    u64 acc = ffma2(w2p[q][0], s[0], b2p[q]);
#pragma unroll
                    for (int k = 1; k < 8; k++) acc = ffma2(w2p[q][k], s[k], acc);
                    float ha, hb; upk(acc, ha, hb);
                    h[q] = pk(fmaxf(ha, 0.0f), fmaxf(hb, 0.0f));
                }

                // layer 3: two independent 2-deep chains
                u64 a0 = ffma2(w3p[0], h[0], b3p);
                u64 a1 = fmul2(w3p[1], h[1]);
                a0 = ffma2(w3p[2], h[2], a0);
                a1 = ffma2(w3p[3], h[3], a1);
                float x0, x1, y0, y1;
                upk(a0, x0, x1); upk(a1, y0, y1);

                red[(g * 8 + u) * 129 + i] = (x0 + x1) + (y0 + y1);
            }
        }
        __syncthreads();

        // spread reduction: thread t sums i-slice [32*(t>>5), +32) of bb = t&31
        {
            const int rb = i & 31, rq = i >> 5;
            const float* rr = &red[rb * 129 + rq * 32];
            float s0 = 0.f, s1 = 0.f, s2 = 0.f, s3 = 0.f;
#pragma unroll
            for (int c = 0; c < 32; c += 4) {
                s0 += rr[c + 0]; s1 += rr[c + 1];
                s2 += rr[c + 2]; s3 += rr[c + 3];
            }
            pr[rq * 33 + rb] = (s0 + s1) + (s2 + s3);
        }
        __syncthreads();

        // 4-way combine + store (one warp; 3 adds each, overlapped with next sub)
        if (i < 32) {
            float r = (pr[i] + pr[33 + i]) + (pr[66 + i] + pr[99 + i]);
            out[(size_t)(chunk * BC + sub * 32 + i) * OUTSZ + o] = r;
        }
    }
}

// ---------------------------------------------------------------------------
extern "C" void kernel_launch(void* const* d_in, const int* in_sizes, int n_in,
                              void* d_out, int out_size) {
    const float* x  = (const float*)d_in[0];
    const float* W1 = (const float*)d_in[1];
    const float* b1 = (const float*)d_in[2];
    const float* W2 = (const float*)d_in[3];
    const float* b2 = (const float*)d_in[4];
    const float* W3 = (const float*)d_in[5];
    const float* b3 = (const float*)d_in[6];
    float* out = (float*)d_out;

    prep_kernel<<<OUTSZ, INSZ>>>(W1, b1, W2, b2, W3, b3);
    mlpkan_main<<<dim3(OUTSZ, NCHUNK), INSZ>>>(x, out);
}